// round 13
// baseline (speedup 1.0000x reference)
#include <cuda_runtime.h>
#include <cuda_fp16.h>
#include <cstdint>

#define NODES_MAX 100000
#define EDGES_MAX 1600000
#define FDIM 64
#define RPB 64             // rows per block
#define RPT 2              // rows per thread
#define CPG 8              // cols per thread
#define PITCH 66           // transposed smem pitch (floats)
#define SCAN_B 1024

// Scratch (allocation-free rule: __device__ globals)
__device__ float  g_dinv[NODES_MAX];
__device__ __half g_xws1[NODES_MAX * FDIM];
__device__ __half g_xws2[NODES_MAX * FDIM];
__device__ int    g_cnt[NODES_MAX];
__device__ int    g_rowptr[NODES_MAX];
__device__ int    g_wptr[NODES_MAX];
__device__ int    g_eidx[EDGES_MAX];
__device__ int    g_bsum[128];

// ---------------------------------------------------------------------------
// CSR build
// ---------------------------------------------------------------------------
__global__ void k_count(const int* __restrict__ dst, int* cnt, int E) {
    int e = blockIdx.x * blockDim.x + threadIdx.x;
    if (e < E) atomicAdd(&cnt[dst[e]], 1);
}
__global__ void k_scan1(const int* __restrict__ cnt, int* rowptr, int* bsum, int n) {
    __shared__ int wsum[32];
    int i = blockIdx.x * SCAN_B + threadIdx.x;
    int lane = threadIdx.x & 31;
    int wid  = threadIdx.x >> 5;
    int v = (i < n) ? cnt[i] : 0;
    int s = v;
    #pragma unroll
    for (int off = 1; off < 32; off <<= 1) {
        int t = __shfl_up_sync(0xffffffffu, s, off);
        if (lane >= off) s += t;
    }
    if (lane == 31) wsum[wid] = s;
    __syncthreads();
    if (wid == 0) {
        int w = wsum[lane];
        #pragma unroll
        for (int off = 1; off < 32; off <<= 1) {
            int t = __shfl_up_sync(0xffffffffu, w, off);
            if (lane >= off) w += t;
        }
        wsum[lane] = w;
    }
    __syncthreads();
    int blockoff = (wid > 0) ? wsum[wid - 1] : 0;
    if (i < n) rowptr[i] = blockoff + s - v;   // exclusive within block
    if (threadIdx.x == SCAN_B - 1) bsum[blockIdx.x] = blockoff + s;
}
// scan finalize: each block locally prefix-sums bsum (nb<=128), then applies.
// Also inits wptr and computes dinv (scan2 folded in).
__global__ void k_scan3(int* rowptr, int* wptr, const int* __restrict__ bsum_in,
                        const int* __restrict__ cnt, float* dinv, int n, int nb) {
    __shared__ int pref[128];
    if (threadIdx.x < nb) pref[threadIdx.x] = bsum_in[threadIdx.x];
    __syncthreads();
    if (threadIdx.x == 0) {
        int run = 0;
        for (int k = 0; k < nb; k++) { int t = pref[k]; pref[k] = run; run += t; }
    }
    __syncthreads();
    int i = blockIdx.x * blockDim.x + threadIdx.x;
    if (i < n) {
        int r = rowptr[i] + pref[i >> 10];
        rowptr[i] = r;
        wptr[i] = r;
        dinv[i] = rsqrtf((float)(cnt[i] + 1));
    }
}
__global__ void k_fill(const int* __restrict__ src, const int* __restrict__ dst,
                       int* wptr, int* eidx, int E) {
    int e = blockIdx.x * blockDim.x + threadIdx.x;
    if (e < E) {
        int d = dst[e];
        int p = atomicAdd(&wptr[d], 1);
        eidx[p] = src[e];
    }
}

// ---------------------------------------------------------------------------
// Pairwise-interleaved warp gather: two independent accumulator chains so a
// warp keeps ~8 loads in flight while halving serial depth per node pair.
// Lane owns cols (2*lane, 2*lane+1). deg>32 tails handled separately (rare).
// ---------------------------------------------------------------------------
__device__ __forceinline__ void gather_pair(
        int nodeA, int nodeB, int n, int lane,
        const int* __restrict__ rowptr, const int* __restrict__ cnt,
        const int* __restrict__ eidx, const __half2* __restrict__ xws,
        float2& accA, float2& accB) {
    const bool vA = nodeA < n;
    const bool vB = nodeB < n;
    int startA = 0, degA = 0, startB = 0, degB = 0;
    if (vA) { startA = __ldg(&rowptr[nodeA]); degA = __ldg(&cnt[nodeA]); }
    if (vB) { startB = __ldg(&rowptr[nodeB]); degB = __ldg(&cnt[nodeB]); }
    accA = vA ? __half22float2(__ldg(&xws[nodeA * 32 + lane])) : make_float2(0.f, 0.f);
    accB = vB ? __half22float2(__ldg(&xws[nodeB * 32 + lane])) : make_float2(0.f, 0.f);

    int mA = min(32, degA);
    int mB = min(32, degB);
    int eA = (lane < mA) ? __ldg(&eidx[startA + lane]) : 0;
    int eB = (lane < mB) ? __ldg(&eidx[startB + lane]) : 0;
    int mmax = max(mA, mB);

    for (int j = 0; j < mmax; j += 4) {
        int sA[4], sB[4];
        #pragma unroll
        for (int u = 0; u < 4; u++) {
            sA[u] = __shfl_sync(0xffffffffu, eA, j + u);
            sB[u] = __shfl_sync(0xffffffffu, eB, j + u);
        }
        float2 va[4], vb[4];
        #pragma unroll
        for (int u = 0; u < 4; u++)
            if (j + u < mA) va[u] = __half22float2(__ldg(&xws[sA[u] * 32 + lane]));
        #pragma unroll
        for (int u = 0; u < 4; u++)
            if (j + u < mB) vb[u] = __half22float2(__ldg(&xws[sB[u] * 32 + lane]));
        #pragma unroll
        for (int u = 0; u < 4; u++)
            if (j + u < mA) { accA.x += va[u].x; accA.y += va[u].y; }
        #pragma unroll
        for (int u = 0; u < 4; u++)
            if (j + u < mB) { accB.x += vb[u].x; accB.y += vb[u].y; }
    }

    // rare tails (deg > 32)
    for (int base = 32; base < degA; base += 32) {
        int m = min(32, degA - base);
        int e = (lane < m) ? __ldg(&eidx[startA + base + lane]) : 0;
        for (int j = 0; j < m; j++) {
            int s = __shfl_sync(0xffffffffu, e, j);
            float2 v = __half22float2(__ldg(&xws[s * 32 + lane]));
            accA.x += v.x; accA.y += v.y;
        }
    }
    for (int base = 32; base < degB; base += 32) {
        int m = min(32, degB - base);
        int e = (lane < m) ? __ldg(&eidx[startB + base + lane]) : 0;
        for (int j = 0; j < m; j++) {
            int s = __shfl_sync(0xffffffffu, e, j);
            float2 v = __half22float2(__ldg(&xws[s * 32 + lane]));
            accB.x += v.x; accB.y += v.y;
        }
    }
}

// ---------------------------------------------------------------------------
// Layer-1 GEMM: xws1[row] = half((x[row] @ W1) * dinv[row])
// ---------------------------------------------------------------------------
__global__ void __launch_bounds__(256, 6) k_gemm1(
        const float* __restrict__ in, const float* __restrict__ W,
        const float* __restrict__ dinv, __half* __restrict__ xws, int n) {
    __shared__ float Ws[FDIM * FDIM];
    __shared__ float rbT[FDIM * PITCH];
    const int lane = threadIdx.x;
    const int cg   = threadIdx.y;
    const int tid  = cg * 32 + lane;
    const int row0 = blockIdx.x * RPB;

    {
        const float4* W4 = (const float4*)W;
        float4* Ws4 = (float4*)Ws;
        #pragma unroll
        for (int i = tid; i < FDIM * FDIM / 4; i += 256) Ws4[i] = W4[i];
    }
    #pragma unroll
    for (int i = tid; i < RPB * FDIM; i += 256) {
        int r = i >> 6, c = i & 63;
        int row = row0 + r;
        rbT[c * PITCH + r] = (row < n) ? in[row * FDIM + c] : 0.0f;
    }
    __syncthreads();

    float acc[RPT][CPG];
    #pragma unroll
    for (int i = 0; i < RPT; i++)
        #pragma unroll
        for (int j = 0; j < CPG; j++) acc[i][j] = 0.0f;

    #pragma unroll
    for (int k = 0; k < FDIM; k++) {
        float2 a  = *(const float2*)&rbT[k * PITCH + lane * RPT];
        float4 w0 = *(const float4*)&Ws[k * FDIM + cg * CPG];
        float4 w1 = *(const float4*)&Ws[k * FDIM + cg * CPG + 4];
        const float ar[RPT] = {a.x, a.y};
        #pragma unroll
        for (int i = 0; i < RPT; i++) {
            acc[i][0] = fmaf(ar[i], w0.x, acc[i][0]);
            acc[i][1] = fmaf(ar[i], w0.y, acc[i][1]);
            acc[i][2] = fmaf(ar[i], w0.z, acc[i][2]);
            acc[i][3] = fmaf(ar[i], w0.w, acc[i][3]);
            acc[i][4] = fmaf(ar[i], w1.x, acc[i][4]);
            acc[i][5] = fmaf(ar[i], w1.y, acc[i][5]);
            acc[i][6] = fmaf(ar[i], w1.z, acc[i][6]);
            acc[i][7] = fmaf(ar[i], w1.w, acc[i][7]);
        }
    }

    #pragma unroll
    for (int i = 0; i < RPT; i++) {
        int row = row0 + lane * RPT + i;
        if (row >= n) break;
        float di = dinv[row];
        __half2 h[4];
        h[0] = __floats2half2_rn(acc[i][0] * di, acc[i][1] * di);
        h[1] = __floats2half2_rn(acc[i][2] * di, acc[i][3] * di);
        h[2] = __floats2half2_rn(acc[i][4] * di, acc[i][5] * di);
        h[3] = __floats2half2_rn(acc[i][6] * di, acc[i][7] * di);
        *(uint4*)&xws[row * FDIM + cg * CPG] = *(uint4*)h;
    }
}

// ---------------------------------------------------------------------------
// Fused gather + layer-2 GEMM:
//   v[r] = relu(dinv[r] * gather(xws1, r) + b1)
//   xws2[r] = half((v @ W2) * dinv[r])
// ---------------------------------------------------------------------------
__global__ void __launch_bounds__(256, 5) k_ggemm(
        const int* __restrict__ rowptr, const int* __restrict__ cnt,
        const int* __restrict__ eidx, const float* __restrict__ dinv,
        const __half2* __restrict__ xin, const float* __restrict__ bias,
        const float* __restrict__ W, __half* __restrict__ xout, int n) {
    __shared__ float Ws[FDIM * FDIM];
    __shared__ float tT[FDIM * PITCH];
    const int lane = threadIdx.x;
    const int cg   = threadIdx.y;
    const int tid  = cg * 32 + lane;
    const int row0 = blockIdx.x * RPB;

    {
        const float4* W4 = (const float4*)W;
        float4* Ws4 = (float4*)Ws;
        #pragma unroll
        for (int i = tid; i < FDIM * FDIM / 4; i += 256) Ws4[i] = W4[i];
    }

    const float b0 = __ldg(&bias[lane * 2]);
    const float b1 = __ldg(&bias[lane * 2 + 1]);
    #pragma unroll 1
    for (int pr = 0; pr < 4; pr++) {
        int r = cg * 8 + pr * 2;
        int nodeA = row0 + r;
        int nodeB = nodeA + 1;
        float2 aA, aB;
        gather_pair(nodeA, nodeB, n, lane, rowptr, cnt, eidx, xin, aA, aB);
        float2 vA = make_float2(0.f, 0.f), vB = make_float2(0.f, 0.f);
        if (nodeA < n) {
            float nd = __ldg(&dinv[nodeA]);
            vA.x = fmaxf(fmaf(aA.x, nd, b0), 0.0f);
            vA.y = fmaxf(fmaf(aA.y, nd, b1), 0.0f);
        }
        if (nodeB < n) {
            float nd = __ldg(&dinv[nodeB]);
            vB.x = fmaxf(fmaf(aB.x, nd, b0), 0.0f);
            vB.y = fmaxf(fmaf(aB.y, nd, b1), 0.0f);
        }
        tT[(lane * 2) * PITCH + r]         = vA.x;
        tT[(lane * 2 + 1) * PITCH + r]     = vA.y;
        tT[(lane * 2) * PITCH + r + 1]     = vB.x;
        tT[(lane * 2 + 1) * PITCH + r + 1] = vB.y;
    }
    __syncthreads();

    float acc[RPT][CPG];
    #pragma unroll
    for (int i = 0; i < RPT; i++)
        #pragma unroll
        for (int j = 0; j < CPG; j++) acc[i][j] = 0.0f;

    #pragma unroll
    for (int k = 0; k < FDIM; k++) {
        float2 a  = *(const float2*)&tT[k * PITCH + lane * RPT];
        float4 w0 = *(const float4*)&Ws[k * FDIM + cg * CPG];
        float4 w1 = *(const float4*)&Ws[k * FDIM + cg * CPG + 4];
        const float ar[RPT] = {a.x, a.y};
        #pragma unroll
        for (int i = 0; i < RPT; i++) {
            acc[i][0] = fmaf(ar[i], w0.x, acc[i][0]);
            acc[i][1] = fmaf(ar[i], w0.y, acc[i][1]);
            acc[i][2] = fmaf(ar[i], w0.z, acc[i][2]);
            acc[i][3] = fmaf(ar[i], w0.w, acc[i][3]);
            acc[i][4] = fmaf(ar[i], w1.x, acc[i][4]);
            acc[i][5] = fmaf(ar[i], w1.y, acc[i][5]);
            acc[i][6] = fmaf(ar[i], w1.z, acc[i][6]);
            acc[i][7] = fmaf(ar[i], w1.w, acc[i][7]);
        }
    }

    #pragma unroll
    for (int i = 0; i < RPT; i++) {
        int row = row0 + lane * RPT + i;
        if (row >= n) break;
        float di = dinv[row];
        __half2 h[4];
        h[0] = __floats2half2_rn(acc[i][0] * di, acc[i][1] * di);
        h[1] = __floats2half2_rn(acc[i][2] * di, acc[i][3] * di);
        h[2] = __floats2half2_rn(acc[i][4] * di, acc[i][5] * di);
        h[3] = __floats2half2_rn(acc[i][6] * di, acc[i][7] * di);
        *(uint4*)&xout[row * FDIM + cg * CPG] = *(uint4*)h;
    }
}

// ---------------------------------------------------------------------------
// Fused gather + head MLP:
//   v = relu(dinv * gather(xws2) + b2); h = relu(v @ dW1 + db1);
//   out = h @ dW2 + db2
// ---------------------------------------------------------------------------
__global__ void __launch_bounds__(256, 5) k_ghead(
        const int* __restrict__ rowptr, const int* __restrict__ cnt,
        const int* __restrict__ eidx, const float* __restrict__ dinv,
        const __half2* __restrict__ xin, const float* __restrict__ b2,
        const float* __restrict__ dW1, const float* __restrict__ db1,
        const float* __restrict__ dW2, const float* __restrict__ db2,
        float* __restrict__ out, int n) {
    __shared__ float sW1[FDIM * FDIM];
    __shared__ float sW2[FDIM * 16];
    __shared__ float sb[FDIM + 16];           // db1 | db2
    __shared__ float tT[FDIM * PITCH];
    const int lane = threadIdx.x;
    const int cg   = threadIdx.y;
    const int tid  = cg * 32 + lane;
    const int row0 = blockIdx.x * RPB;

    {
        const float4* a4 = (const float4*)dW1;
        float4* s4 = (float4*)sW1;
        #pragma unroll
        for (int i = tid; i < FDIM * FDIM / 4; i += 256) s4[i] = a4[i];
        const float4* b4 = (const float4*)dW2;
        float4* t4 = (float4*)sW2;
        if (tid < FDIM * 16 / 4) t4[tid] = b4[tid];
        if (tid < 64)       sb[tid] = db1[tid];
        else if (tid < 80)  sb[tid] = db2[tid - 64];
    }

    const float b0 = __ldg(&b2[lane * 2]);
    const float b1 = __ldg(&b2[lane * 2 + 1]);
    #pragma unroll 1
    for (int pr = 0; pr < 4; pr++) {
        int r = cg * 8 + pr * 2;
        int nodeA = row0 + r;
        int nodeB = nodeA + 1;
        float2 aA, aB;
        gather_pair(nodeA, nodeB, n, lane, rowptr, cnt, eidx, xin, aA, aB);
        float2 vA = make_float2(0.f, 0.f), vB = make_float2(0.f, 0.f);
        if (nodeA < n) {
            float nd = __ldg(&dinv[nodeA]);
            vA.x = fmaxf(fmaf(aA.x, nd, b0), 0.0f);
            vA.y = fmaxf(fmaf(aA.y, nd, b1), 0.0f);
        }
        if (nodeB < n) {
            float nd = __ldg(&dinv[nodeB]);
            vB.x = fmaxf(fmaf(aB.x, nd, b0), 0.0f);
            vB.y = fmaxf(fmaf(aB.y, nd, b1), 0.0f);
        }
        tT[(lane * 2) * PITCH + r]         = vA.x;
        tT[(lane * 2 + 1) * PITCH + r]     = vA.y;
        tT[(lane * 2) * PITCH + r + 1]     = vB.x;
        tT[(lane * 2 + 1) * PITCH + r + 1] = vB.y;
    }
    __syncthreads();

    // h = relu(v @ dW1 + db1)
    float acc[RPT][CPG];
    #pragma unroll
    for (int i = 0; i < RPT; i++)
        #pragma unroll
        for (int j = 0; j < CPG; j++) acc[i][j] = 0.0f;

    #pragma unroll
    for (int k = 0; k < FDIM; k++) {
        float2 a  = *(const float2*)&tT[k * PITCH + lane * RPT];
        float4 w0 = *(const float4*)&sW1[k * FDIM + cg * CPG];
        float4 w1 = *(const float4*)&sW1[k * FDIM + cg * CPG + 4];
        const float ar[RPT] = {a.x, a.y};
        #pragma unroll
        for (int i = 0; i < RPT; i++) {
            acc[i][0] = fmaf(ar[i], w0.x, acc[i][0]);
            acc[i][1] = fmaf(ar[i], w0.y, acc[i][1]);
            acc[i][2] = fmaf(ar[i], w0.z, acc[i][2]);
            acc[i][3] = fmaf(ar[i], w0.w, acc[i][3]);
            acc[i][4] = fmaf(ar[i], w1.x, acc[i][4]);
            acc[i][5] = fmaf(ar[i], w1.y, acc[i][5]);
            acc[i][6] = fmaf(ar[i], w1.z, acc[i][6]);
            acc[i][7] = fmaf(ar[i], w1.w, acc[i][7]);
        }
    }
    __syncthreads();   // vT reads complete before overwrite with h

    #pragma unroll
    for (int i = 0; i < RPT; i++)
        #pragma unroll
        for (int j = 0; j < CPG; j++)
            tT[(cg * CPG + j) * PITCH + lane * RPT + i] =
                fmaxf(acc[i][j] + sb[cg * CPG + j], 0.0f);
    __syncthreads();

    // out = h @ dW2 + db2
    {
        float o[RPT][2];
        #pragma unroll
        for (int i = 0; i < RPT; i++) { o[i][0] = 0.0f; o[i][1] = 0.0f; }
        #pragma unroll
        for (int k = 0; k < FDIM; k++) {
            float2 a = *(const float2*)&tT[k * PITCH + lane * RPT];
            float2 w = *(const float2*)&sW2[k * 16 + cg * 2];
            const float ar[RPT] = {a.x, a.y};
            #pragma unroll
            for (int i = 0; i < RPT; i++) {
                o[i][0] = fmaf(ar[i], w.x, o[i][0]);
                o[i][1] = fmaf(ar[i], w.y, o[i][1]);
            }
        }
        #pragma unroll
        for (int i = 0; i < RPT; i++) {
            int row = row0 + lane * RPT + i;
            if (row >= n) break;
            float2 v;
            v.x = o[i][0] + sb[64 + cg * 2];
            v.y = o[i][1] + sb[64 + cg * 2 + 1];
            *(float2*)&out[row * 16 + cg * 2] = v;
        }
    }
}

// ---------------------------------------------------------------------------
extern "C" void kernel_launch(void* const* d_in, const int* in_sizes, int n_in,
                              void* d_out, int out_size) {
    const float* x   = (const float*)d_in[0];
    const int*   ei  = (const int*)  d_in[1];
    const float* W1  = (const float*)d_in[2];
    const float* b1  = (const float*)d_in[3];
    const float* W2  = (const float*)d_in[4];
    const float* b2  = (const float*)d_in[5];
    const float* dW1 = (const float*)d_in[6];
    const float* db1 = (const float*)d_in[7];
    const float* dW2 = (const float*)d_in[8];
    const float* db2 = (const float*)d_in[9];
    float* out = (float*)d_out;

    const int N = in_sizes[0] / FDIM;
    const int E = in_sizes[1] / 2;
    const int* src = ei;
    const int* dst = ei + E;

    float* dinv;
    __half *xws1, *xws2;
    int *cnt, *rowptr, *wptr, *eidx, *bsum;
    cudaGetSymbolAddress((void**)&dinv,   g_dinv);
    cudaGetSymbolAddress((void**)&xws1,   g_xws1);
    cudaGetSymbolAddress((void**)&xws2,   g_xws2);
    cudaGetSymbolAddress((void**)&cnt,    g_cnt);
    cudaGetSymbolAddress((void**)&rowptr, g_rowptr);
    cudaGetSymbolAddress((void**)&wptr,   g_wptr);
    cudaGetSymbolAddress((void**)&eidx,   g_eidx);
    cudaGetSymbolAddress((void**)&bsum,   g_bsum);

    const int TB = 256;
    const int nScanBlocks = (N + SCAN_B - 1) / SCAN_B;
    dim3 gblk(32, 8);
    const int rowBlocks = (N + RPB - 1) / RPB;

    // CSR build (scan2 folded into scan3)
    cudaMemsetAsync(cnt, 0, N * sizeof(int));
    k_count<<<(E + TB - 1) / TB, TB>>>(dst, cnt, E);
    k_scan1<<<nScanBlocks, SCAN_B>>>(cnt, rowptr, bsum, N);
    k_scan3<<<(N + TB - 1) / TB, TB>>>(rowptr, wptr, bsum, cnt, dinv, N, nScanBlocks);
    k_fill <<<(E + TB - 1) / TB, TB>>>(src, dst, wptr, eidx, E);

    // layer 1 GEMM -> fused gather+layer2 GEMM -> fused gather+head
    k_gemm1<<<rowBlocks, gblk>>>(x, W1, dinv, xws1, N);
    k_ggemm<<<rowBlocks, gblk>>>(rowptr, cnt, eidx, dinv,
                                 (const __half2*)xws1, b1, W2, xws2, N);
    k_ghead<<<rowBlocks, gblk>>>(rowptr, cnt, eidx, dinv,
                                 (const __half2*)xws2, b2, dW1, db1, dW2, db2,
                                 out, N);
}